// round 13
// baseline (speedup 1.0000x reference)
#include <cuda_runtime.h>
#include <cuda_fp16.h>

// Ngram_24618752540965 fixed shapes:
//   V = 4096 (vocab), M = 4 (markov order), B = 8, L = 2048
//   fan_in = M*(V+1) = 16388
//   out[p, v] = b[v] + sum_k W[v, k*(V+1) + x[p,k]]
//   x[p,k] = (l >= 3-k) ? idx[p - (3-k)] : V   (pad token = V), l = p % L
//   (source token at q feeds position p iff q >= row_start(p))
#define VOCAB   4096
#define MORD    4
#define FAN     (MORD * (VOCAB + 1))   // 16388
#define LLEN    2048
#define NPOS    16384                  // B * L

// v-chunking: per chunk the fp16 transposed slice is 16388 x 1024 x 2B
// = 33.6 MB. Two slices live at once under pipelining (67 MB < 126 MB L2).
#define VCHUNK  1024
#define NCHUNK  (VOCAB / VCHUNK)       // 4

#define POS_PER_BLK 8
#define G_GATHER (NPOS / POS_PER_BLK)                 // 2048 long gather blocks
#define G_TPOSE  ((VCHUNK / 32) * ((FAN + 31) / 32))  // 32*513 = 16416 blocks
// Mixed stage: interleave 1 gather : 8 transpose so gather blocks (4x longer)
// persist on SMs while short transpose blocks stream through remaining slots.
#define G_INTER  (9 * G_GATHER)                       // 18432
#define G_MIXED  (G_INTER + (G_TPOSE - 8 * G_GATHER)) // 18432 + 32 = 18464

// 134 MB scratch: transposed fp16 weights, g_wh[f][v] = (half)W[v][f].
// fp32 accumulation; entries ~U(+-0.0078) -> fp16 RMS rel err ~2.8e-4.
__device__ __half g_wh[(size_t)FAN * VOCAB];

__device__ __forceinline__ void acc8(float* acc, uint4 q) {
    float2 f;
    f = __half22float2(*(const __half2*)&q.x); acc[0] += f.x; acc[1] += f.y;
    f = __half22float2(*(const __half2*)&q.y); acc[2] += f.x; acc[3] += f.y;
    f = __half22float2(*(const __half2*)&q.z); acc[4] += f.x; acc[5] += f.y;
    f = __half22float2(*(const __half2*)&q.w); acc[6] += f.x; acc[7] += f.y;
}

// ---------------------------------------------------------------------------
// Gather: block = 8 positions (2 substreams x 4-position loop), 128 lanes
// cover VCHUNK (8 halves per lane). Bias lives in registers for the whole
// block; the 7-token sliding window is loaded once per substream.
// ---------------------------------------------------------------------------
__device__ __forceinline__ void do_gather(
    int gid, int c_gather,
    const int* __restrict__ idx, const float* __restrict__ bias,
    float* __restrict__ out)
{
    const int vbase = c_gather * VCHUNK;
    const int sub = threadIdx.x >> 7;            // substream 0/1
    const int t   = threadIdx.x & 127;           // v lane (8 halves)
    const int p0  = gid * POS_PER_BLK + sub * 4; // first of 4 positions
    const int row0 = p0 & ~(LLEN - 1);           // sequence-row start

    // Sliding token window for positions p0..p0+3 (sources p0-3 .. p0+3).
    int tok[7];
    #pragma unroll
    for (int j = 0; j < 7; j++) {
        const int q = p0 + j - 3;
        tok[j] = (q >= row0) ? idx[q] : VOCAB;
    }

    // Bias slice for this lane, held in registers across all positions.
    const float4* __restrict__ b4 = (const float4*)(bias + vbase);
    const float4 bb0 = b4[2 * t];
    const float4 bb1 = b4[2 * t + 1];

    #pragma unroll 1
    for (int i = 0; i < 4; i++) {
        const int p = p0 + i;
        // x_k(p) = tok[i + k]
        const uint4* __restrict__ r0 = (const uint4*)
            &g_wh[(size_t)(0 * (VOCAB + 1) + tok[i + 0]) * VOCAB + vbase];
        const uint4* __restrict__ r1 = (const uint4*)
            &g_wh[(size_t)(1 * (VOCAB + 1) + tok[i + 1]) * VOCAB + vbase];
        const uint4* __restrict__ r2 = (const uint4*)
            &g_wh[(size_t)(2 * (VOCAB + 1) + tok[i + 2]) * VOCAB + vbase];
        const uint4* __restrict__ r3 = (const uint4*)
            &g_wh[(size_t)(3 * (VOCAB + 1) + tok[i + 3]) * VOCAB + vbase];

        const uint4 q0 = __ldcg(r0 + t);
        const uint4 q1 = __ldcg(r1 + t);
        const uint4 q2 = __ldcg(r2 + t);
        const uint4 q3 = __ldcg(r3 + t);

        float acc[8] = {bb0.x, bb0.y, bb0.z, bb0.w,
                        bb1.x, bb1.y, bb1.z, bb1.w};
        acc8(acc, q0);
        acc8(acc, q1);
        acc8(acc, q2);
        acc8(acc, q3);

        float4* __restrict__ o4 = (float4*)(out + (size_t)p * VOCAB + vbase);
        __stcs(o4 + 2 * t,     make_float4(acc[0], acc[1], acc[2], acc[3]));
        __stcs(o4 + 2 * t + 1, make_float4(acc[4], acc[5], acc[6], acc[7]));
    }
}

// ---------------------------------------------------------------------------
// Transpose: 32x32 tile of W -> fp16 g_wh (smem staged, conflict-free).
// ---------------------------------------------------------------------------
__device__ __forceinline__ void do_tpose(
    int tid, int c_tpose, const float* __restrict__ W, float (*tile)[33])
{
    const int v0 = c_tpose * VCHUNK + (tid & 31) * 32;   // v tile (fastest)
    const int c0 = (tid >> 5) * 32;                      // fan tile (0..512)
    const int tx = threadIdx.x & 7;
    const int ty = threadIdx.x >> 3;

    // Load W[v0+ty][c0+4tx..+3] (streaming; FAN % 4 == 0, no straddle)
    const int c = c0 + 4 * tx;
    if (c < FAN) {
        const float4 w = __ldcs(
            (const float4*)&W[(size_t)(v0 + ty) * FAN + c]);
        tile[4 * tx + 0][ty] = w.x;
        tile[4 * tx + 1][ty] = w.y;
        tile[4 * tx + 2][ty] = w.z;
        tile[4 * tx + 3][ty] = w.w;
    }
    __syncthreads();

    // Store g_wh[c0+ty][v0+4tx..+3] as one packed 8B store (stay in L2)
    const int f = c0 + ty;
    if (f < FAN) {
        const __half2 h0 = __floats2half2_rn(tile[ty][4 * tx + 0],
                                             tile[ty][4 * tx + 1]);
        const __half2 h1 = __floats2half2_rn(tile[ty][4 * tx + 2],
                                             tile[ty][4 * tx + 3]);
        uint2 o;
        o.x = *(const unsigned int*)&h0;
        o.y = *(const unsigned int*)&h1;
        *(uint2*)&g_wh[(size_t)f * VOCAB + v0 + 4 * tx] = o;
    }
}

// ---------------------------------------------------------------------------
// Stage kernel. Mixed stages interleave 1 gather : 8 transpose by blockIdx%9;
// long-running gather blocks overlap the DRAM-streaming transpose blocks
// temporally on each SM. Single-role stages map blocks directly.
// ---------------------------------------------------------------------------
__global__ void __launch_bounds__(256) ngram_stage_kernel(
    const float* __restrict__ W,
    const int*   __restrict__ idx,
    const float* __restrict__ bias,
    float*       __restrict__ out,
    int c_gather, int c_tpose)
{
    __shared__ float tile[32][33];
    const unsigned bx = blockIdx.x;

    if (c_gather >= 0 && c_tpose >= 0) {
        if (bx < G_INTER) {
            const unsigned r = bx % 9u;
            const unsigned q = bx / 9u;
            if (r == 0) {
                do_gather((int)q, c_gather, idx, bias, out);
            } else {
                do_tpose((int)(q * 8u + (r - 1u)), c_tpose, W, tile);
            }
        } else {
            do_tpose((int)(8u * G_GATHER + (bx - G_INTER)), c_tpose, W, tile);
        }
    } else if (c_tpose >= 0) {
        do_tpose((int)bx, c_tpose, W, tile);
    } else {
        do_gather((int)bx, c_gather, idx, bias, out);
    }
}

// ---------------------------------------------------------------------------
// Inputs: idx [B*L] int32, W [V*FAN] f32, b [V] f32.  Output: [B*L*V] f32.
// Pipeline over chunks: stage s gathers chunk s-1 while transposing chunk s.
//   stage 0:        transpose(0)                      grid = G_TPOSE
//   stages 1..3:    gather(s-1) + transpose(s)        grid = G_MIXED
//   stage 4:        gather(3)                         grid = G_GATHER
// ---------------------------------------------------------------------------
extern "C" void kernel_launch(void* const* d_in, const int* in_sizes, int n_in,
                              void* d_out, int out_size) {
    const int*   idx  = (const int*)d_in[0];
    const float* W    = (const float*)d_in[1];
    const float* bias = (const float*)d_in[2];
    float*       out  = (float*)d_out;

    ngram_stage_kernel<<<G_TPOSE, 256>>>(W, idx, bias, out, -1, 0);
    for (int s = 1; s < NCHUNK; s++) {
        ngram_stage_kernel<<<G_MIXED, 256>>>(W, idx, bias, out, s - 1, s);
    }
    ngram_stage_kernel<<<G_GATHER, 256>>>(W, idx, bias, out, NCHUNK - 1, -1);
}

// round 17
// speedup vs baseline: 1.3141x; 1.3141x over previous
#include <cuda_runtime.h>
#include <cuda_fp16.h>

// Ngram_24618752540965 fixed shapes:
//   V = 4096 (vocab), M = 4 (markov order), B = 8, L = 2048
//   fan_in = M*(V+1) = 16388
//   out[p, v] = b[v] + sum_k W[v, k*(V+1) + x[p,k]]
//   x[p,k] = (l >= 3-k) ? idx[p - (3-k)] : V   (pad token = V), l = p % L
#define VOCAB   4096
#define MORD    4
#define FAN     (MORD * (VOCAB + 1))   // 16388
#define LLEN    2048
#define NPOS    16384                  // B * L

// v-chunking: per chunk the fp16 transposed slice is 16388 x 1024 x 2B
// = 33.6 MB. Two slices live at once under pipelining (67 MB < 126 MB L2).
#define VCHUNK  1024
#define NCHUNK  (VOCAB / VCHUNK)       // 4

#define G_GATHER (NPOS / 2)                            // 8192 gather blocks
#define FT2      ((FAN + 63) / 64)                     // 257 f-pair tiles
#define G_TPOSE  ((VCHUNK / 32) * FT2)                 // 32*257 = 8224 blocks
#define G_PAIRED (2 * G_GATHER)                        // 16384 interleaved
#define G_MIXED  (G_PAIRED + (G_TPOSE - G_GATHER))     // 16384 + 32 = 16416

// 134 MB scratch: transposed fp16 weights, g_wh[f][v] = (half)W[v][f].
// fp32 accumulation; entries ~U(+-0.0078) -> fp16 RMS rel err ~2.8e-4.
__device__ __half g_wh[(size_t)FAN * VOCAB];

__device__ __forceinline__ void acc8(float* acc, uint4 q) {
    float2 f;
    f = __half22float2(*(const __half2*)&q.x); acc[0] += f.x; acc[1] += f.y;
    f = __half22float2(*(const __half2*)&q.y); acc[2] += f.x; acc[3] += f.y;
    f = __half22float2(*(const __half2*)&q.z); acc[4] += f.x; acc[5] += f.y;
    f = __half22float2(*(const __half2*)&q.w); acc[6] += f.x; acc[7] += f.y;
}

// ---------------------------------------------------------------------------
// Gather: 2 positions x 128 lanes (R10 structure). Table addressing uses
// 32-bit element offsets (<< 12 within 67M-element table) to avoid 64-bit
// IMAD chains; base pointer added once by LEA.
// ---------------------------------------------------------------------------
__device__ __forceinline__ void do_gather(
    int gid, int c_gather,
    const int* __restrict__ idx, const float* __restrict__ bias,
    float* __restrict__ out)
{
    const unsigned vbase = (unsigned)(c_gather * VCHUNK);
    const int p = gid * 2 + (threadIdx.x >> 7);
    const int t = threadIdx.x & 127;
    const int l = p & (LLEN - 1);

    const unsigned x0 = (l >= 3) ? (unsigned)idx[p - 3] : VOCAB;
    const unsigned x1 = (l >= 2) ? (unsigned)idx[p - 2] : VOCAB;
    const unsigned x2 = (l >= 1) ? (unsigned)idx[p - 1] : VOCAB;
    const unsigned x3 = (unsigned)idx[p];

    // 32-bit element offsets into g_wh (max 16388*4096 < 2^31)
    const unsigned o0 = ((0u * (VOCAB + 1) + x0) << 12) + vbase;
    const unsigned o1 = ((1u * (VOCAB + 1) + x1) << 12) + vbase;
    const unsigned o2 = ((2u * (VOCAB + 1) + x2) << 12) + vbase;
    const unsigned o3 = ((3u * (VOCAB + 1) + x3) << 12) + vbase;

    const uint4 q0 = __ldcg((const uint4*)(g_wh + o0) + t);
    const uint4 q1 = __ldcg((const uint4*)(g_wh + o1) + t);
    const uint4 q2 = __ldcg((const uint4*)(g_wh + o2) + t);
    const uint4 q3 = __ldcg((const uint4*)(g_wh + o3) + t);

    const float4* __restrict__ b4 = (const float4*)(bias + vbase);
    const float4 bb0 = b4[2 * t];
    const float4 bb1 = b4[2 * t + 1];

    float acc[8] = {bb0.x, bb0.y, bb0.z, bb0.w, bb1.x, bb1.y, bb1.z, bb1.w};
    acc8(acc, q0);
    acc8(acc, q1);
    acc8(acc, q2);
    acc8(acc, q3);

    float4* __restrict__ o4 = (float4*)(out + (size_t)p * VOCAB + vbase);
    __stcs(o4 + 2 * t,     make_float4(acc[0], acc[1], acc[2], acc[3]));
    __stcs(o4 + 2 * t + 1, make_float4(acc[4], acc[5], acc[6], acc[7]));
}

// ---------------------------------------------------------------------------
// Transpose: one block handles 32 v x 64 f (two 32x32 subtiles) -> fp16 g_wh.
// Two independent LDG.128 per thread (MLP=2) hide DRAM latency; same
// conflict-free 32x33 banking as before, duplicated.
// ---------------------------------------------------------------------------
__device__ __forceinline__ void do_tpose(
    int tid, int c_tpose, const float* __restrict__ W,
    float (*tile)[32][33])
{
    const int v0 = c_tpose * VCHUNK + (tid & 31) * 32;   // v tile (fastest)
    const int c0 = (tid >> 5) * 64;                      // f pair-tile origin
    const int tx = threadIdx.x & 7;
    const int ty = threadIdx.x >> 3;

    const float* __restrict__ wrow = W + (size_t)(v0 + ty) * FAN;

    #pragma unroll
    for (int s = 0; s < 2; s++) {
        const int c = c0 + 32 * s + 4 * tx;
        if (c < FAN) {                 // FAN % 4 == 0 -> no straddle
            const float4 w = __ldcs((const float4*)(wrow + c));
            tile[s][4 * tx + 0][ty] = w.x;
            tile[s][4 * tx + 1][ty] = w.y;
            tile[s][4 * tx + 2][ty] = w.z;
            tile[s][4 * tx + 3][ty] = w.w;
        }
    }
    __syncthreads();

    #pragma unroll
    for (int s = 0; s < 2; s++) {
        const int f = c0 + 32 * s + ty;
        if (f < FAN) {
            const __half2 h0 = __floats2half2_rn(tile[s][ty][4 * tx + 0],
                                                 tile[s][ty][4 * tx + 1]);
            const __half2 h1 = __floats2half2_rn(tile[s][ty][4 * tx + 2],
                                                 tile[s][ty][4 * tx + 3]);
            uint2 o;
            o.x = *(const unsigned int*)&h0;
            o.y = *(const unsigned int*)&h1;
            *(uint2*)&g_wh[(size_t)f * VOCAB + v0 + 4 * tx] = o;
        }
    }
}

// ---------------------------------------------------------------------------
// Stage kernel. Mixed stages interleave 1 gather : 1 transpose by blockIdx
// parity (uniform block lengths, every wave carries both populations).
// ---------------------------------------------------------------------------
__global__ void __launch_bounds__(256) ngram_stage_kernel(
    const float* __restrict__ W,
    const int*   __restrict__ idx,
    const float* __restrict__ bias,
    float*       __restrict__ out,
    int c_gather, int c_tpose)
{
    __shared__ float tile[2][32][33];
    const unsigned bx = blockIdx.x;

    if (c_gather >= 0 && c_tpose >= 0) {
        if (bx < G_PAIRED) {
            if ((bx & 1u) == 0u) {
                do_gather((int)(bx >> 1), c_gather, idx, bias, out);
            } else {
                do_tpose((int)(bx >> 1), c_tpose, W, tile);
            }
        } else {
            do_tpose((int)(G_GATHER + (bx - G_PAIRED)), c_tpose, W, tile);
        }
    } else if (c_tpose >= 0) {
        do_tpose((int)bx, c_tpose, W, tile);
    } else {
        do_gather((int)bx, c_gather, idx, bias, out);
    }
}

// ---------------------------------------------------------------------------
// Inputs: idx [B*L] int32, W [V*FAN] f32, b [V] f32.  Output: [B*L*V] f32.
// Pipeline over chunks: stage s gathers chunk s-1 while transposing chunk s.
//   stage 0:        transpose(0)                      grid = G_TPOSE
//   stages 1..3:    gather(s-1) + transpose(s)        grid = G_MIXED
//   stage 4:        gather(3)                         grid = G_GATHER
// ---------------------------------------------------------------------------
extern "C" void kernel_launch(void* const* d_in, const int* in_sizes, int n_in,
                              void* d_out, int out_size) {
    const int*   idx  = (const int*)d_in[0];
    const float* W    = (const float*)d_in[1];
    const float* bias = (const float*)d_in[2];
    float*       out  = (float*)d_out;

    ngram_stage_kernel<<<G_TPOSE, 256>>>(W, idx, bias, out, -1, 0);
    for (int s = 1; s < NCHUNK; s++) {
        ngram_stage_kernel<<<G_MIXED, 256>>>(W, idx, bias, out, s - 1, s);
    }
    ngram_stage_kernel<<<G_GATHER, 256>>>(W, idx, bias, out, NCHUNK - 1, -1);
}